// round 1
// baseline (speedup 1.0000x reference)
#include <cuda_runtime.h>
#include <math.h>

// Problem constants
#define NWIN 2048
#define NTOK 64
#define CDIM 384
#define NH   12
#define HD   32
#define XPAD 388   // x tile row stride in smem (floats)

// Device scratch (allowed: __device__ globals, no runtime allocation)
__device__ float g_attn_out[(size_t)NWIN * NTOK * CDIM];   // [B, N, C] pre-projection
__device__ float g_bias[NH * NTOK * NTOK];                 // [H, N, M] relative bias table

// ---------------------------------------------------------------------------
// Kernel 1: relative position bias table via the tiny MLP
// bias[h][n][m] = (relu(rel(n,m) @ w1 + b1) @ w2 + b2)[h]
// coords: n = i*16 + j*4 + k  (meshgrid 'ij' over (4,4,4))
// ---------------------------------------------------------------------------
__global__ void bias_kernel(const float* __restrict__ w1, const float* __restrict__ b1,
                            const float* __restrict__ w2, const float* __restrict__ b2) {
    int idx = blockIdx.x * blockDim.x + threadIdx.x;  // (n, m) pair
    if (idx >= NTOK * NTOK) return;
    int n = idx / NTOK, m = idx % NTOK;
    float r0 = (float)((n >> 4) & 3) - (float)((m >> 4) & 3);
    float r1 = (float)((n >> 2) & 3) - (float)((m >> 2) & 3);
    float r2 = (float)(n & 3)        - (float)(m & 3);

    float outh[NH];
#pragma unroll
    for (int h = 0; h < NH; h++) outh[h] = b2[h];
    for (int j = 0; j < 64; j++) {
        float hj = fmaf(r0, w1[0 * 64 + j], fmaf(r1, w1[1 * 64 + j], fmaf(r2, w1[2 * 64 + j], b1[j])));
        hj = fmaxf(hj, 0.0f);
#pragma unroll
        for (int h = 0; h < NH; h++) outh[h] = fmaf(hj, w2[j * NH + h], outh[h]);
    }
#pragma unroll
    for (int h = 0; h < NH; h++) g_bias[h * NTOK * NTOK + idx] = outh[h];
}

// ---------------------------------------------------------------------------
// Kernel 2: fused QKV + attention per window.
// Block = 1 window, 256 threads = 2 teams of 128. Team processes one head at
// a time (6 iterations). x tile lives in smem for the whole block.
// ---------------------------------------------------------------------------
extern __shared__ float sm[];

__global__ void __launch_bounds__(256, 1)
attn_kernel(const float* __restrict__ x,
            const float* __restrict__ qkv_w,
            const float* __restrict__ qkv_b) {
    const int b    = blockIdx.x;
    const int t    = threadIdx.x;      // 0..255
    const int team = t >> 7;           // 0/1
    const int lt   = t & 127;          // 0..127
    const int tx   = lt & 15;          // 0..15
    const int ty   = lt >> 4;          // 0..7

    float* xs       = sm;                                            // 64 x 388
    float* teambase = sm + NTOK * XPAD + team * (3 * 64 * 33 + 64 * 65);
    float* qs = teambase;              // 64 x 33
    float* ks = qs + 64 * 33;          // 64 x 33
    float* vs = ks + 64 * 33;          // 64 x 33
    float* S  = vs + 64 * 33;          // 64 x 65

    // ---- stage x[b] (64x384) into smem, float4 coalesced ----
    const float* xg = x + (size_t)b * NTOK * CDIM;
    for (int i = t; i < NTOK * CDIM / 4; i += 256) {
        int row = i / (CDIM / 4);
        int c4  = i % (CDIM / 4);
        float4 v4 = ((const float4*)xg)[i];
        float* dst = xs + row * XPAD + c4 * 4;
        dst[0] = v4.x; dst[1] = v4.y; dst[2] = v4.z; dst[3] = v4.w;
    }
    __syncthreads();

    const float scale = 0.17677669529663687f;  // 1/sqrt(32)

    for (int hi = 0; hi < 6; hi++) {
        const int h = hi * 2 + team;

        // ==== QKV: out 64x96 per head. Thread tile: rows {ty+8r}, cols {tx+16j} (j<6)
        float acc[8][6];
#pragma unroll
        for (int r = 0; r < 8; r++)
#pragma unroll
            for (int j = 0; j < 6; j++) acc[r][j] = 0.0f;

        int gcol[6];
#pragma unroll
        for (int j = 0; j < 6; j++) {
            int part = j >> 1;                 // 0:q 1:k 2:v
            int c    = tx + 16 * (j & 1);      // 0..31 within head
            gcol[j]  = part * CDIM + h * HD + c;
        }

        for (int k = 0; k < CDIM; k++) {
            float wv[6];
            const float* wrow = qkv_w + (size_t)k * (3 * CDIM);
#pragma unroll
            for (int j = 0; j < 6; j++) wv[j] = wrow[gcol[j]];
#pragma unroll
            for (int r = 0; r < 8; r++) {
                float xv = xs[(ty + 8 * r) * XPAD + k];
#pragma unroll
                for (int j = 0; j < 6; j++) acc[r][j] = fmaf(xv, wv[j], acc[r][j]);
            }
        }
#pragma unroll
        for (int j = 0; j < 6; j++) {
            float bb = qkv_b[gcol[j]];
            int part = j >> 1;
            int c    = tx + 16 * (j & 1);
            float* dst = (part == 0) ? qs : ((part == 1) ? ks : vs);
#pragma unroll
            for (int r = 0; r < 8; r++)
                dst[(ty + 8 * r) * 33 + c] = acc[r][j] + bb;
        }
        __syncthreads();

        // ==== S = scale * q k^T + bias : 64x64. Thread tile rows {ty+8r}, cols {tx+16j} (j<4)
        {
            float sacc[8][4];
#pragma unroll
            for (int r = 0; r < 8; r++)
#pragma unroll
                for (int j = 0; j < 4; j++) sacc[r][j] = 0.0f;

            for (int d = 0; d < HD; d++) {
                float qv[8], kv[4];
#pragma unroll
                for (int r = 0; r < 8; r++) qv[r] = qs[(ty + 8 * r) * 33 + d];
#pragma unroll
                for (int j = 0; j < 4; j++) kv[j] = ks[(tx + 16 * j) * 33 + d];
#pragma unroll
                for (int r = 0; r < 8; r++)
#pragma unroll
                    for (int j = 0; j < 4; j++) sacc[r][j] = fmaf(qv[r], kv[j], sacc[r][j]);
            }
            const float* bh = g_bias + h * NTOK * NTOK;
#pragma unroll
            for (int r = 0; r < 8; r++) {
                int n = ty + 8 * r;
#pragma unroll
                for (int j = 0; j < 4; j++) {
                    int m = tx + 16 * j;
                    S[n * 65 + m] = fmaf(sacc[r][j], scale, bh[n * 64 + m]);
                }
            }
        }
        __syncthreads();

        // ==== softmax over rows (64 rows, one per thread lt<64)
        if (lt < 64) {
            float* Sr = S + lt * 65;
            float mx = -1e30f;
#pragma unroll 8
            for (int m = 0; m < 64; m++) mx = fmaxf(mx, Sr[m]);
            float sum = 0.0f;
#pragma unroll 8
            for (int m = 0; m < 64; m++) { float e = __expf(Sr[m] - mx); Sr[m] = e; sum += e; }
            float inv = 1.0f / sum;
#pragma unroll 8
            for (int m = 0; m < 64; m++) Sr[m] *= inv;
        }
        __syncthreads();

        // ==== O_h = P @ v : 64x32. Thread tile rows {ty+8r}, cols {tx+16j} (j<2)
        {
            float oacc[8][2];
#pragma unroll
            for (int r = 0; r < 8; r++) { oacc[r][0] = 0.0f; oacc[r][1] = 0.0f; }

            for (int m = 0; m < 64; m++) {
                float vv0 = vs[m * 33 + tx];
                float vv1 = vs[m * 33 + tx + 16];
#pragma unroll
                for (int r = 0; r < 8; r++) {
                    float sv = S[(ty + 8 * r) * 65 + m];
                    oacc[r][0] = fmaf(sv, vv0, oacc[r][0]);
                    oacc[r][1] = fmaf(sv, vv1, oacc[r][1]);
                }
            }
            float* og = g_attn_out + (size_t)b * NTOK * CDIM + h * HD;
#pragma unroll
            for (int r = 0; r < 8; r++) {
                int n = ty + 8 * r;
                og[(size_t)n * CDIM + tx]      = oacc[r][0];
                og[(size_t)n * CDIM + tx + 16] = oacc[r][1];
            }
        }
        __syncthreads();
    }
}

// ---------------------------------------------------------------------------
// Kernel 3: projection GEMM  out[M,384] = g_attn_out[M,384] @ proj_w[384,384] + proj_b
// Tile 64x64x16, 256 threads, 4x4 micro-tile.
// ---------------------------------------------------------------------------
__global__ void __launch_bounds__(256)
proj_kernel(const float* __restrict__ w, const float* __restrict__ bias,
            float* __restrict__ out) {
    __shared__ float As[64][17];
    __shared__ float Bs[16][64];

    const int bm = blockIdx.x;   // M/64 = 2048
    const int bn = blockIdx.y;   // 384/64 = 6
    const int t  = threadIdx.x;
    const int tx = t & 15, ty = t >> 4;

    const float* A = g_attn_out + (size_t)bm * 64 * CDIM;

    float acc[4][4];
#pragma unroll
    for (int i = 0; i < 4; i++)
#pragma unroll
        for (int j = 0; j < 4; j++) acc[i][j] = 0.0f;

    for (int kt = 0; kt < CDIM; kt += 16) {
        {   // load A tile 64x16
            int row = t >> 2, c4 = t & 3;
            float4 v4 = *(const float4*)(A + (size_t)row * CDIM + kt + c4 * 4);
            As[row][c4 * 4 + 0] = v4.x; As[row][c4 * 4 + 1] = v4.y;
            As[row][c4 * 4 + 2] = v4.z; As[row][c4 * 4 + 3] = v4.w;
        }
        {   // load W tile 16x64
            int kr = t >> 4, c4 = t & 15;
            float4 v4 = *(const float4*)(w + (size_t)(kt + kr) * CDIM + bn * 64 + c4 * 4);
            *(float4*)&Bs[kr][c4 * 4] = v4;
        }
        __syncthreads();
#pragma unroll
        for (int k = 0; k < 16; k++) {
            float a[4];
#pragma unroll
            for (int i = 0; i < 4; i++) a[i] = As[ty * 4 + i][k];
            float4 b4 = *(float4*)&Bs[k][tx * 4];
#pragma unroll
            for (int i = 0; i < 4; i++) {
                acc[i][0] = fmaf(a[i], b4.x, acc[i][0]);
                acc[i][1] = fmaf(a[i], b4.y, acc[i][1]);
                acc[i][2] = fmaf(a[i], b4.z, acc[i][2]);
                acc[i][3] = fmaf(a[i], b4.w, acc[i][3]);
            }
        }
        __syncthreads();
    }

    float4 bv = *(const float4*)(bias + bn * 64 + tx * 4);
#pragma unroll
    for (int i = 0; i < 4; i++) {
        size_t orow = (size_t)bm * 64 + ty * 4 + i;
        float4 o;
        o.x = acc[i][0] + bv.x; o.y = acc[i][1] + bv.y;
        o.z = acc[i][2] + bv.z; o.w = acc[i][3] + bv.w;
        *(float4*)(out + orow * CDIM + bn * 64 + tx * 4) = o;
    }
}

// ---------------------------------------------------------------------------
extern "C" void kernel_launch(void* const* d_in, const int* in_sizes, int n_in,
                              void* d_out, int out_size) {
    const float* x      = (const float*)d_in[0];
    const float* qkv_w  = (const float*)d_in[1];
    const float* qkv_b  = (const float*)d_in[2];
    const float* proj_w = (const float*)d_in[3];
    const float* proj_b = (const float*)d_in[4];
    const float* mlp_w1 = (const float*)d_in[5];
    const float* mlp_b1 = (const float*)d_in[6];
    const float* mlp_w2 = (const float*)d_in[7];
    const float* mlp_b2 = (const float*)d_in[8];

    // 1) bias table
    bias_kernel<<<16, 256>>>(mlp_w1, mlp_b1, mlp_w2, mlp_b2);

    // 2) fused qkv + attention
    size_t smem = (size_t)(NTOK * XPAD + 2 * (3 * 64 * 33 + 64 * 65)) * sizeof(float);
    cudaFuncSetAttribute(attn_kernel, cudaFuncAttributeMaxDynamicSharedMemorySize, (int)smem);
    attn_kernel<<<NWIN, 256, smem>>>(x, qkv_w, qkv_b);

    // 3) projection
    dim3 pgrid(NWIN, CDIM / 64);   // M/64 = 2048, N/64 = 6
    proj_kernel<<<pgrid, 256>>>(proj_w, proj_b, (float*)d_out);
}

// round 3
// speedup vs baseline: 5.2835x; 5.2835x over previous
#include <cuda_runtime.h>
#include <cstdint>
#include <math.h>

// Problem constants
#define NWIN 2048
#define NTOK 64
#define CDIM 384
#define NH   12
#define HD   32
#define MTOT (NWIN * NTOK)          // 131072 rows

// ---------------------------------------------------------------------------
// Device scratch
// ---------------------------------------------------------------------------
__device__ float g_qkv[(size_t)MTOT * 3 * CDIM];      // [M, 1152]
__device__ float g_attn[(size_t)MTOT * CDIM];          // [M, 384]
__device__ float g_bias[NH * NTOK * NTOK];             // [H, N, M]
__device__ float g_wt_qkv[(size_t)3 * CDIM * CDIM];    // [1152, 384] K-major
__device__ float g_wt_proj[(size_t)CDIM * CDIM];       // [384, 384]  K-major

__device__ __forceinline__ uint32_t f2tf32(float v) {
    uint32_t r;
    asm("cvt.rna.tf32.f32 %0, %1;" : "=r"(r) : "f"(v));
    return r;
}

__device__ __forceinline__ void mma_tf32(float* d, const uint32_t* a, const uint32_t* b) {
    asm volatile(
        "mma.sync.aligned.m16n8k8.row.col.f32.tf32.tf32.f32 "
        "{%0,%1,%2,%3}, {%4,%5,%6,%7}, {%8,%9}, {%0,%1,%2,%3};"
        : "+f"(d[0]), "+f"(d[1]), "+f"(d[2]), "+f"(d[3])
        : "r"(a[0]), "r"(a[1]), "r"(a[2]), "r"(a[3]), "r"(b[0]), "r"(b[1]));
}

// ---------------------------------------------------------------------------
// Kernel: weight transpose  out[N,K] = in[K,N]
// ---------------------------------------------------------------------------
__global__ void transpose_kernel(const float* __restrict__ in, float* __restrict__ out,
                                 int K, int N) {
    __shared__ float tl[32][33];
    int n0 = blockIdx.x * 32, k0 = blockIdx.y * 32;
    int x = threadIdx.x, y = threadIdx.y;
#pragma unroll
    for (int j = y; j < 32; j += 8) tl[j][x] = in[(size_t)(k0 + j) * N + n0 + x];
    __syncthreads();
#pragma unroll
    for (int j = y; j < 32; j += 8) out[(size_t)(n0 + j) * K + k0 + x] = tl[x][j];
}

// ---------------------------------------------------------------------------
// Kernel: relative position bias table via the tiny MLP
// ---------------------------------------------------------------------------
__global__ void bias_kernel(const float* __restrict__ w1, const float* __restrict__ b1,
                            const float* __restrict__ w2, const float* __restrict__ b2) {
    int idx = blockIdx.x * blockDim.x + threadIdx.x;
    if (idx >= NTOK * NTOK) return;
    int n = idx / NTOK, m = idx % NTOK;
    float r0 = (float)((n >> 4) & 3) - (float)((m >> 4) & 3);
    float r1 = (float)((n >> 2) & 3) - (float)((m >> 2) & 3);
    float r2 = (float)(n & 3)        - (float)(m & 3);

    float outh[NH];
#pragma unroll
    for (int h = 0; h < NH; h++) outh[h] = b2[h];
    for (int j = 0; j < 64; j++) {
        float hj = fmaf(r0, w1[j], fmaf(r1, w1[64 + j], fmaf(r2, w1[128 + j], b1[j])));
        hj = fmaxf(hj, 0.0f);
#pragma unroll
        for (int h = 0; h < NH; h++) outh[h] = fmaf(hj, w2[j * NH + h], outh[h]);
    }
#pragma unroll
    for (int h = 0; h < NH; h++) g_bias[h * NTOK * NTOK + idx] = outh[h];
}

// ---------------------------------------------------------------------------
// Kernel: tf32 mma.sync GEMM  out[M, ldc] = A[M,384] @ Bt[N,384]^T + bias
// CTA tile 128x128, 8 warps (2 M x 4 N), warp tile 64x32, K-chunk 32.
// A, B staged in smem with row pad 36 (bank = lane on fragment loads).
// grid = (N/128, M/128), blockIdx.x fastest so same-A CTAs co-run (L2 reuse).
// ---------------------------------------------------------------------------
#define KC 32
#define PAD 36

__global__ void __launch_bounds__(256, 2)
gemm_tf32(const float* __restrict__ A, const float* __restrict__ Bt,
          const float* __restrict__ bias, float* __restrict__ out, int ldc) {
    __shared__ uint32_t As[128 * PAD];
    __shared__ uint32_t Bs[128 * PAD];

    const int t    = threadIdx.x;
    const int wid  = t >> 5, lane = t & 31;
    const int wm   = wid & 1;          // 0..1  (64-row slab)
    const int wn   = wid >> 1;         // 0..3  (32-col slab)
    const int n0   = blockIdx.x * 128;
    const int m0   = blockIdx.y * 128;

    const int lrow = lane >> 2;        // 0..7
    const int lcol = lane & 3;         // 0..3

    float acc[4][4][4];                // [mt][nt][reg]
#pragma unroll
    for (int i = 0; i < 4; i++)
#pragma unroll
        for (int j = 0; j < 4; j++)
#pragma unroll
            for (int r = 0; r < 4; r++) acc[i][j][r] = 0.0f;

    // load indices: 256 threads x 8 float4 = 2048 float4 = one 128x32 tile x2
    const int ldr = t >> 3;            // 0..31 base row
    const int ldc4 = t & 7;            // 0..7 -> cols 4*ldc4

    for (int ch = 0; ch < CDIM / KC; ch++) {
        const int k0 = ch * KC;
#pragma unroll
        for (int i = 0; i < 4; i++) {
            int row = ldr + i * 32;
            float4 av = *(const float4*)(A  + (size_t)(m0 + row) * CDIM + k0 + ldc4 * 4);
            float4 bv = *(const float4*)(Bt + (size_t)(n0 + row) * CDIM + k0 + ldc4 * 4);
            uint32_t* ad = As + row * PAD + ldc4 * 4;
            uint32_t* bd = Bs + row * PAD + ldc4 * 4;
            ad[0] = f2tf32(av.x); ad[1] = f2tf32(av.y); ad[2] = f2tf32(av.z); ad[3] = f2tf32(av.w);
            bd[0] = f2tf32(bv.x); bd[1] = f2tf32(bv.y); bd[2] = f2tf32(bv.z); bd[3] = f2tf32(bv.w);
        }
        __syncthreads();

#pragma unroll
        for (int ks = 0; ks < KC / 8; ks++) {
            const int kk = ks * 8;
            uint32_t afr[4][4], bfr[4][2];
#pragma unroll
            for (int mt = 0; mt < 4; mt++) {
                const uint32_t* ap = As + (wm * 64 + mt * 16 + lrow) * PAD + kk + lcol;
                afr[mt][0] = ap[0];
                afr[mt][1] = ap[8 * PAD];
                afr[mt][2] = ap[4];
                afr[mt][3] = ap[8 * PAD + 4];
            }
#pragma unroll
            for (int nt = 0; nt < 4; nt++) {
                const uint32_t* bp = Bs + (wn * 32 + nt * 8 + lrow) * PAD + kk + lcol;
                bfr[nt][0] = bp[0];
                bfr[nt][1] = bp[4];
            }
#pragma unroll
            for (int mt = 0; mt < 4; mt++)
#pragma unroll
                for (int nt = 0; nt < 4; nt++)
                    mma_tf32(acc[mt][nt], afr[mt], bfr[nt]);
        }
        __syncthreads();
    }

    // Epilogue: c0,c1 at (row, col*2 / +1); c2,c3 at (row+8, ...)
#pragma unroll
    for (int mt = 0; mt < 4; mt++) {
#pragma unroll
        for (int nt = 0; nt < 4; nt++) {
            int row = m0 + wm * 64 + mt * 16 + lrow;
            int col = n0 + wn * 32 + nt * 8 + lcol * 2;
            float2 bv = *(const float2*)(bias + col);
            float2 o0, o1;
            o0.x = acc[mt][nt][0] + bv.x; o0.y = acc[mt][nt][1] + bv.y;
            o1.x = acc[mt][nt][2] + bv.x; o1.y = acc[mt][nt][3] + bv.y;
            *(float2*)(out + (size_t)row * ldc + col)        = o0;
            *(float2*)(out + (size_t)(row + 8) * ldc + col)  = o1;
        }
    }
}

// ---------------------------------------------------------------------------
// Kernel: attention per window (reads precomputed qkv). Block = 1 window,
// 256 threads = 2 teams of 128; team handles one head at a time.
// ---------------------------------------------------------------------------
extern __shared__ float asm_[];

__global__ void __launch_bounds__(256, 1)
attn_kernel() {
    const int b    = blockIdx.x;
    const int t    = threadIdx.x;
    const int team = t >> 7;
    const int lt   = t & 127;
    const int tx   = lt & 15;
    const int ty   = lt >> 4;

    float* teambase = asm_ + team * (3 * 64 * 33 + 64 * 65);
    float* qs = teambase;
    float* ks = qs + 64 * 33;
    float* vs = ks + 64 * 33;
    float* S  = vs + 64 * 33;

    const float scale = 0.17677669529663687f;  // 1/sqrt(32)
    const float* qkvb = g_qkv + (size_t)b * NTOK * (3 * CDIM);

    for (int hi = 0; hi < 6; hi++) {
        const int h = hi * 2 + team;
        const int qoff = h * HD, koff = CDIM + h * HD, voff = 2 * CDIM + h * HD;

        for (int i = lt; i < 512; i += 128) {
            int n = i >> 3, c4 = i & 7;
            const float* rowp = qkvb + (size_t)n * (3 * CDIM);
            float4 qv = *(const float4*)(rowp + qoff + c4 * 4);
            float4 kv = *(const float4*)(rowp + koff + c4 * 4);
            float4 vv = *(const float4*)(rowp + voff + c4 * 4);
            float* qd = qs + n * 33 + c4 * 4;
            float* kd = ks + n * 33 + c4 * 4;
            float* vd = vs + n * 33 + c4 * 4;
            qd[0] = qv.x; qd[1] = qv.y; qd[2] = qv.z; qd[3] = qv.w;
            kd[0] = kv.x; kd[1] = kv.y; kd[2] = kv.z; kd[3] = kv.w;
            vd[0] = vv.x; vd[1] = vv.y; vd[2] = vv.z; vd[3] = vv.w;
        }
        __syncthreads();

        {
            float sacc[8][4];
#pragma unroll
            for (int r = 0; r < 8; r++)
#pragma unroll
                for (int j = 0; j < 4; j++) sacc[r][j] = 0.0f;
            for (int d = 0; d < HD; d++) {
                float qv[8], kv[4];
#pragma unroll
                for (int r = 0; r < 8; r++) qv[r] = qs[(ty + 8 * r) * 33 + d];
#pragma unroll
                for (int j = 0; j < 4; j++) kv[j] = ks[(tx + 16 * j) * 33 + d];
#pragma unroll
                for (int r = 0; r < 8; r++)
#pragma unroll
                    for (int j = 0; j < 4; j++) sacc[r][j] = fmaf(qv[r], kv[j], sacc[r][j]);
            }
            const float* bh = g_bias + h * NTOK * NTOK;
#pragma unroll
            for (int r = 0; r < 8; r++) {
                int n = ty + 8 * r;
#pragma unroll
                for (int j = 0; j < 4; j++) {
                    int m = tx + 16 * j;
                    S[n * 65 + m] = fmaf(sacc[r][j], scale, bh[n * 64 + m]);
                }
            }
        }
        __syncthreads();

        if (lt < 64) {
            float* Sr = S + lt * 65;
            float mx = -1e30f;
#pragma unroll 8
            for (int m = 0; m < 64; m++) mx = fmaxf(mx, Sr[m]);
            float sum = 0.0f;
#pragma unroll 8
            for (int m = 0; m < 64; m++) { float e = __expf(Sr[m] - mx); Sr[m] = e; sum += e; }
            float inv = 1.0f / sum;
#pragma unroll 8
            for (int m = 0; m < 64; m++) Sr[m] *= inv;
        }
        __syncthreads();

        {
            float oacc[8][2];
#pragma unroll
            for (int r = 0; r < 8; r++) { oacc[r][0] = 0.0f; oacc[r][1] = 0.0f; }
            for (int m = 0; m < 64; m++) {
                float vv0 = vs[m * 33 + tx];
                float vv1 = vs[m * 33 + tx + 16];
#pragma unroll
                for (int r = 0; r < 8; r++) {
                    float sv = S[(ty + 8 * r) * 65 + m];
                    oacc[r][0] = fmaf(sv, vv0, oacc[r][0]);
                    oacc[r][1] = fmaf(sv, vv1, oacc[r][1]);
                }
            }
            float* og = g_attn + (size_t)b * NTOK * CDIM + h * HD;
#pragma unroll
            for (int r = 0; r < 8; r++) {
                int n = ty + 8 * r;
                og[(size_t)n * CDIM + tx]      = oacc[r][0];
                og[(size_t)n * CDIM + tx + 16] = oacc[r][1];
            }
        }
        __syncthreads();
    }
}

// ---------------------------------------------------------------------------
extern "C" void kernel_launch(void* const* d_in, const int* in_sizes, int n_in,
                              void* d_out, int out_size) {
    const float* x      = (const float*)d_in[0];
    const float* qkv_w  = (const float*)d_in[1];
    const float* qkv_b  = (const float*)d_in[2];
    const float* proj_w = (const float*)d_in[3];
    const float* proj_b = (const float*)d_in[4];
    const float* mlp_w1 = (const float*)d_in[5];
    const float* mlp_b1 = (const float*)d_in[6];
    const float* mlp_w2 = (const float*)d_in[7];
    const float* mlp_b2 = (const float*)d_in[8];

    float* wt_qkv;  cudaGetSymbolAddress((void**)&wt_qkv,  g_wt_qkv);
    float* wt_proj; cudaGetSymbolAddress((void**)&wt_proj, g_wt_proj);
    float* qkv;     cudaGetSymbolAddress((void**)&qkv,     g_qkv);
    float* attn;    cudaGetSymbolAddress((void**)&attn,    g_attn);

    // weight transposes to K-major (N-major rows, K contiguous)
    transpose_kernel<<<dim3(3 * CDIM / 32, CDIM / 32), dim3(32, 8)>>>(qkv_w, wt_qkv, CDIM, 3 * CDIM);
    transpose_kernel<<<dim3(CDIM / 32, CDIM / 32), dim3(32, 8)>>>(proj_w, wt_proj, CDIM, CDIM);

    // relative-position bias table
    bias_kernel<<<16, 256>>>(mlp_w1, mlp_b1, mlp_w2, mlp_b2);

    // QKV GEMM: [131072,384] @ [384,1152]
    gemm_tf32<<<dim3(9, MTOT / 128), 256>>>(x, wt_qkv, qkv_b, qkv, 3 * CDIM);

    // attention
    size_t asmem = (size_t)2 * (3 * 64 * 33 + 64 * 65) * sizeof(float);
    cudaFuncSetAttribute(attn_kernel, cudaFuncAttributeMaxDynamicSharedMemorySize, (int)asmem);
    attn_kernel<<<NWIN, 256, asmem>>>();

    // projection GEMM: [131072,384] @ [384,384] -> d_out
    gemm_tf32<<<dim3(3, MTOT / 128), 256>>>(attn, wt_proj, proj_b, (float*)d_out, CDIM);
}

// round 4
// speedup vs baseline: 6.8517x; 1.2968x over previous
#include <cuda_runtime.h>
#include <cstdint>
#include <math.h>

// Problem constants
#define NWIN 2048
#define NTOK 64
#define CDIM 384
#define NH   12
#define HD   32
#define MTOT (NWIN * NTOK)          // 131072 rows

// ---------------------------------------------------------------------------
// Device scratch
// ---------------------------------------------------------------------------
__device__ float g_qkv[(size_t)MTOT * 3 * CDIM];      // [M, 1152]
__device__ float g_attn[(size_t)MTOT * CDIM];          // [M, 384]
__device__ float g_bias[NH * NTOK * NTOK];             // [H, N, M]
__device__ float g_wt_qkv[(size_t)3 * CDIM * CDIM];    // [1152, 384] K-major
__device__ float g_wt_proj[(size_t)CDIM * CDIM];       // [384, 384]  K-major

__device__ __forceinline__ uint32_t f2tf32(float v) {
    uint32_t r;
    asm("cvt.rna.tf32.f32 %0, %1;" : "=r"(r) : "f"(v));
    return r;
}
__device__ __forceinline__ void mma_tf32(float* d, const uint32_t* a, const uint32_t* b) {
    asm volatile(
        "mma.sync.aligned.m16n8k8.row.col.f32.tf32.tf32.f32 "
        "{%0,%1,%2,%3}, {%4,%5,%6,%7}, {%8,%9}, {%0,%1,%2,%3};"
        : "+f"(d[0]), "+f"(d[1]), "+f"(d[2]), "+f"(d[3])
        : "r"(a[0]), "r"(a[1]), "r"(a[2]), "r"(a[3]), "r"(b[0]), "r"(b[1]));
}
__device__ __forceinline__ uint32_t smem_u32(const void* p) {
    uint32_t a;
    asm("{ .reg .u64 t; cvta.to.shared.u64 t, %1; cvt.u32.u64 %0, t; }" : "=r"(a) : "l"(p));
    return a;
}
__device__ __forceinline__ void cp16(uint32_t dst, const void* src) {
    asm volatile("cp.async.cg.shared.global [%0], [%1], 16;" :: "r"(dst), "l"(src));
}
#define CP_COMMIT() asm volatile("cp.async.commit_group;" ::: "memory")
#define CP_WAIT(N)  asm volatile("cp.async.wait_group %0;" :: "n"(N) : "memory")

// ---------------------------------------------------------------------------
// Kernel: weight transpose  out[N,K] = in[K,N]
// ---------------------------------------------------------------------------
__global__ void transpose_kernel(const float* __restrict__ in, float* __restrict__ out,
                                 int K, int N) {
    __shared__ float tl[32][33];
    int n0 = blockIdx.x * 32, k0 = blockIdx.y * 32;
    int x = threadIdx.x, y = threadIdx.y;
#pragma unroll
    for (int j = y; j < 32; j += 8) tl[j][x] = in[(size_t)(k0 + j) * N + n0 + x];
    __syncthreads();
#pragma unroll
    for (int j = y; j < 32; j += 8) out[(size_t)(n0 + j) * K + k0 + x] = tl[x][j];
}

// ---------------------------------------------------------------------------
// Kernel: relative position bias table via the tiny MLP
// ---------------------------------------------------------------------------
__global__ void bias_kernel(const float* __restrict__ w1, const float* __restrict__ b1,
                            const float* __restrict__ w2, const float* __restrict__ b2) {
    int idx = blockIdx.x * blockDim.x + threadIdx.x;
    if (idx >= NTOK * NTOK) return;
    int n = idx / NTOK, m = idx % NTOK;
    float r0 = (float)((n >> 4) & 3) - (float)((m >> 4) & 3);
    float r1 = (float)((n >> 2) & 3) - (float)((m >> 2) & 3);
    float r2 = (float)(n & 3)        - (float)(m & 3);

    float outh[NH];
#pragma unroll
    for (int h = 0; h < NH; h++) outh[h] = b2[h];
    for (int j = 0; j < 64; j++) {
        float hj = fmaf(r0, w1[j], fmaf(r1, w1[64 + j], fmaf(r2, w1[128 + j], b1[j])));
        hj = fmaxf(hj, 0.0f);
#pragma unroll
        for (int h = 0; h < NH; h++) outh[h] = fmaf(hj, w2[j * NH + h], outh[h]);
    }
#pragma unroll
    for (int h = 0; h < NH; h++) g_bias[h * NTOK * NTOK + idx] = outh[h];
}

// ---------------------------------------------------------------------------
// Kernel: tf32 mma.sync GEMM, cp.async double-buffered.
// out[M, ldc] = A[M,384] @ Bt[N,384]^T + bias
// CTA tile 128x128, 8 warps (2Mx4N), warp tile 64x32, K-chunk 32.
// smem: XOR-swizzled 16B groups, raw fp32; cvt->tf32 at fragment load.
// dsm layout (floats): [A s0: 4096][A s1: 4096][B s0: 4096][B s1: 4096]
// ---------------------------------------------------------------------------
#define KC 32
#define NCH (CDIM / KC)   // 12

__global__ void __launch_bounds__(256, 2)
gemm_tf32(const float* __restrict__ A, const float* __restrict__ Bt,
          const float* __restrict__ bias, float* __restrict__ out, int ldc) {
    extern __shared__ float dsm[];

    const int t    = threadIdx.x;
    const int wid  = t >> 5, lane = t & 31;
    const int wm   = wid & 1;          // 0..1
    const int wn   = wid >> 1;         // 0..3
    const int n0   = blockIdx.x * 128;
    const int m0   = blockIdx.y * 128;
    const int lrow = lane >> 2;        // 0..7
    const int lcol = lane & 3;         // 0..3

    const uint32_t sbase = smem_u32(dsm);

    float acc[4][4][4];
#pragma unroll
    for (int i = 0; i < 4; i++)
#pragma unroll
        for (int j = 0; j < 4; j++)
#pragma unroll
            for (int r = 0; r < 4; r++) acc[i][j][r] = 0.0f;

    const int ldr = t >> 3;            // 0..31
    const int ldg = t & 7;             // 0..7 (16B group)

    // issue one K-chunk into stage st
#define ISSUE(ch, st) do {                                                         \
        int _k0 = (ch) * KC;                                                       \
        _Pragma("unroll")                                                          \
        for (int _i = 0; _i < 4; _i++) {                                           \
            int _row = ldr + _i * 32;                                              \
            int _sg  = ldg ^ (_row & 7);                                           \
            uint32_t _off = (uint32_t)(((st) * 4096 + _row * 32 + _sg * 4) * 4);   \
            cp16(sbase + _off,        A  + (size_t)(m0 + _row) * CDIM + _k0 + ldg * 4); \
            cp16(sbase + 32768 + _off, Bt + (size_t)(n0 + _row) * CDIM + _k0 + ldg * 4); \
        }                                                                          \
        CP_COMMIT();                                                               \
    } while (0)

    ISSUE(0, 0);
    ISSUE(1, 1);

    for (int c = 0; c < NCH; c++) {
        if (c == NCH - 1) { CP_WAIT(0); } else { CP_WAIT(1); }
        __syncthreads();

        const float* As_ = dsm + (c & 1) * 4096;
        const float* Bs_ = dsm + 8192 + (c & 1) * 4096;

#pragma unroll
        for (int ks = 0; ks < KC / 8; ks++) {
            const int kk = ks * 8;
            const int g0 = (kk >> 2) ^ lrow;
            const int g1 = ((kk >> 2) + 1) ^ lrow;
            uint32_t afr[4][4], bfr[4][2];
#pragma unroll
            for (int mt = 0; mt < 4; mt++) {
                int row = wm * 64 + mt * 16 + lrow;
                afr[mt][0] = f2tf32(As_[row * 32 + g0 * 4 + lcol]);
                afr[mt][1] = f2tf32(As_[(row + 8) * 32 + g0 * 4 + lcol]);
                afr[mt][2] = f2tf32(As_[row * 32 + g1 * 4 + lcol]);
                afr[mt][3] = f2tf32(As_[(row + 8) * 32 + g1 * 4 + lcol]);
            }
#pragma unroll
            for (int nt = 0; nt < 4; nt++) {
                int row = wn * 32 + nt * 8 + lrow;
                bfr[nt][0] = f2tf32(Bs_[row * 32 + g0 * 4 + lcol]);
                bfr[nt][1] = f2tf32(Bs_[row * 32 + g1 * 4 + lcol]);
            }
#pragma unroll
            for (int mt = 0; mt < 4; mt++)
#pragma unroll
                for (int nt = 0; nt < 4; nt++)
                    mma_tf32(acc[mt][nt], afr[mt], bfr[nt]);
        }
        __syncthreads();
        if (c + 2 < NCH) ISSUE(c + 2, c & 1);
    }

#pragma unroll
    for (int mt = 0; mt < 4; mt++) {
#pragma unroll
        for (int nt = 0; nt < 4; nt++) {
            int row = m0 + wm * 64 + mt * 16 + lrow;
            int col = n0 + wn * 32 + nt * 8 + lcol * 2;
            float2 bv = *(const float2*)(bias + col);
            float2 o0, o1;
            o0.x = acc[mt][nt][0] + bv.x; o0.y = acc[mt][nt][1] + bv.y;
            o1.x = acc[mt][nt][2] + bv.x; o1.y = acc[mt][nt][3] + bv.y;
            *(float2*)(out + (size_t)row * ldc + col)       = o0;
            *(float2*)(out + (size_t)(row + 8) * ldc + col) = o1;
        }
    }
#undef ISSUE
}
#define GEMM_SMEM (16384 * 4)   // 64 KB

// ---------------------------------------------------------------------------
// Kernel: tensor-core attention per window. Block = 1 window, 256 thr =
// 2 teams x 4 warps; team does one head at a time (6 each).
// Team smem (floats): qs[64][36], ks[64][36], vt[32][68], Ss[64][68] = 11136
// ---------------------------------------------------------------------------
#define TEAM_F 11136
#define ATTN_SMEM (2 * TEAM_F * 4)

__global__ void __launch_bounds__(256, 2)
attn_kernel() {
    extern __shared__ float dsm[];
    const int b    = blockIdx.x;
    const int t    = threadIdx.x;
    const int team = t >> 7;
    const int lt   = t & 127;
    const int w    = lt >> 5;          // warp in team 0..3
    const int lane = t & 31;
    const int lrow = lane >> 2;
    const int lcol = lane & 3;

    float* qs = dsm + team * TEAM_F;   // [64][36]
    float* ks = qs + 64 * 36;          // [64][36]
    float* vt = ks + 64 * 36;          // [32][68]  (d, m)
    float* Ss = vt + 32 * 68;          // [64][68]

    const float scale = 0.17677669529663687f;  // 1/sqrt(32)
    const float* qkvb = g_qkv + (size_t)b * NTOK * (3 * CDIM);

    for (int hi = 0; hi < 6; hi++) {
        const int h = hi * 2 + team;
        const int qoff = h * HD, koff = CDIM + h * HD, voff = 2 * CDIM + h * HD;

        // load q,k row-major; v transposed
        for (int i = lt; i < 512; i += 128) {
            int n = i >> 3, c4 = i & 7;
            const float* rowp = qkvb + (size_t)n * (3 * CDIM);
            float4 qv = *(const float4*)(rowp + qoff + c4 * 4);
            float4 kv = *(const float4*)(rowp + koff + c4 * 4);
            float4 vv = *(const float4*)(rowp + voff + c4 * 4);
            float* qd = qs + n * 36 + c4 * 4;
            float* kd = ks + n * 36 + c4 * 4;
            qd[0] = qv.x; qd[1] = qv.y; qd[2] = qv.z; qd[3] = qv.w;
            kd[0] = kv.x; kd[1] = kv.y; kd[2] = kv.z; kd[3] = kv.w;
            int d0 = c4 * 4;
            vt[(d0 + 0) * 68 + n] = vv.x;
            vt[(d0 + 1) * 68 + n] = vv.y;
            vt[(d0 + 2) * 68 + n] = vv.z;
            vt[(d0 + 3) * 68 + n] = vv.w;
        }
        __syncthreads();

        // ---- S = Q K^T (warp w: rows w*16..w*16+15, all 64 cols)
        float sacc[8][4];
#pragma unroll
        for (int nt = 0; nt < 8; nt++)
#pragma unroll
            for (int r = 0; r < 4; r++) sacc[nt][r] = 0.0f;

#pragma unroll
        for (int kc = 0; kc < 4; kc++) {
            const int kk = kc * 8;
            int row0 = w * 16 + lrow;
            uint32_t af[4];
            af[0] = f2tf32(qs[row0 * 36 + kk + lcol]);
            af[1] = f2tf32(qs[(row0 + 8) * 36 + kk + lcol]);
            af[2] = f2tf32(qs[row0 * 36 + kk + 4 + lcol]);
            af[3] = f2tf32(qs[(row0 + 8) * 36 + kk + 4 + lcol]);
#pragma unroll
            for (int nt = 0; nt < 8; nt++) {
                int krow = nt * 8 + lrow;
                uint32_t bf[2];
                bf[0] = f2tf32(ks[krow * 36 + kk + lcol]);
                bf[1] = f2tf32(ks[krow * 36 + kk + 4 + lcol]);
                mma_tf32(sacc[nt], af, bf);
            }
        }
        // store S*scale + bias
        const float* bh = g_bias + h * NTOK * NTOK;
        {
            int row = w * 16 + lrow;
#pragma unroll
            for (int nt = 0; nt < 8; nt++) {
                int col = nt * 8 + lcol * 2;
                float2 b0 = *(const float2*)(bh + row * 64 + col);
                float2 b1 = *(const float2*)(bh + (row + 8) * 64 + col);
                Ss[row * 68 + col]           = fmaf(sacc[nt][0], scale, b0.x);
                Ss[row * 68 + col + 1]       = fmaf(sacc[nt][1], scale, b0.y);
                Ss[(row + 8) * 68 + col]     = fmaf(sacc[nt][2], scale, b1.x);
                Ss[(row + 8) * 68 + col + 1] = fmaf(sacc[nt][3], scale, b1.y);
            }
        }
        __syncthreads();

        // ---- softmax: 2 threads per row
        {
            int r = lt >> 1;
            float* Sr = Ss + r * 68 + (lt & 1) * 32;
            float mx = -1e30f;
#pragma unroll 8
            for (int m = 0; m < 32; m++) mx = fmaxf(mx, Sr[m]);
            mx = fmaxf(mx, __shfl_xor_sync(0xFFFFFFFFu, mx, 1));
            float sum = 0.0f;
#pragma unroll 8
            for (int m = 0; m < 32; m++) { float e = __expf(Sr[m] - mx); Sr[m] = e; sum += e; }
            sum += __shfl_xor_sync(0xFFFFFFFFu, sum, 1);
            float inv = 1.0f / sum;
#pragma unroll 8
            for (int m = 0; m < 32; m++) Sr[m] *= inv;
        }
        __syncthreads();

        // ---- O = P V  (warp w: rows w*16.., 32 cols; K=64 in chunks of 8)
        float oacc[4][4];
#pragma unroll
        for (int nt = 0; nt < 4; nt++)
#pragma unroll
            for (int r = 0; r < 4; r++) oacc[nt][r] = 0.0f;

#pragma unroll
        for (int kc = 0; kc < 8; kc++) {
            const int kk = kc * 8;
            int row0 = w * 16 + lrow;
            uint32_t pf[4];
            pf[0] = f2tf32(Ss[row0 * 68 + kk + lcol]);
            pf[1] = f2tf32(Ss[(row0 + 8) * 68 + kk + lcol]);
            pf[2] = f2tf32(Ss[row0 * 68 + kk + 4 + lcol]);
            pf[3] = f2tf32(Ss[(row0 + 8) * 68 + kk + 4 + lcol]);
#pragma unroll
            for (int nt = 0; nt < 4; nt++) {
                int dd = nt * 8 + lrow;
                uint32_t vf[2];
                vf[0] = f2tf32(vt[dd * 68 + kk + lcol]);
                vf[1] = f2tf32(vt[dd * 68 + kk + 4 + lcol]);
                mma_tf32(oacc[nt], pf, vf);
            }
        }
        // write O
        {
            float* og = g_attn + (size_t)b * NTOK * CDIM + h * HD;
            int row = w * 16 + lrow;
#pragma unroll
            for (int nt = 0; nt < 4; nt++) {
                int col = nt * 8 + lcol * 2;
                float2 o0 = make_float2(oacc[nt][0], oacc[nt][1]);
                float2 o1 = make_float2(oacc[nt][2], oacc[nt][3]);
                *(float2*)(og + (size_t)row * CDIM + col)       = o0;
                *(float2*)(og + (size_t)(row + 8) * CDIM + col) = o1;
            }
        }
        __syncthreads();
    }
}

// ---------------------------------------------------------------------------
extern "C" void kernel_launch(void* const* d_in, const int* in_sizes, int n_in,
                              void* d_out, int out_size) {
    const float* x      = (const float*)d_in[0];
    const float* qkv_w  = (const float*)d_in[1];
    const float* qkv_b  = (const float*)d_in[2];
    const float* proj_w = (const float*)d_in[3];
    const float* proj_b = (const float*)d_in[4];
    const float* mlp_w1 = (const float*)d_in[5];
    const float* mlp_b1 = (const float*)d_in[6];
    const float* mlp_w2 = (const float*)d_in[7];
    const float* mlp_b2 = (const float*)d_in[8];

    float* wt_qkv;  cudaGetSymbolAddress((void**)&wt_qkv,  g_wt_qkv);
    float* wt_proj; cudaGetSymbolAddress((void**)&wt_proj, g_wt_proj);
    float* qkv;     cudaGetSymbolAddress((void**)&qkv,     g_qkv);
    float* attn;    cudaGetSymbolAddress((void**)&attn,    g_attn);

    transpose_kernel<<<dim3(3 * CDIM / 32, CDIM / 32), dim3(32, 8)>>>(qkv_w, wt_qkv, CDIM, 3 * CDIM);
    transpose_kernel<<<dim3(CDIM / 32, CDIM / 32), dim3(32, 8)>>>(proj_w, wt_proj, CDIM, CDIM);
    bias_kernel<<<16, 256>>>(mlp_w1, mlp_b1, mlp_w2, mlp_b2);

    cudaFuncSetAttribute(gemm_tf32, cudaFuncAttributeMaxDynamicSharedMemorySize, GEMM_SMEM);
    cudaFuncSetAttribute(attn_kernel, cudaFuncAttributeMaxDynamicSharedMemorySize, ATTN_SMEM);

    // QKV GEMM: [131072,384] @ [384,1152]
    gemm_tf32<<<dim3(9, MTOT / 128), 256, GEMM_SMEM>>>(x, wt_qkv, qkv_b, qkv, 3 * CDIM);

    // attention (tensor cores)
    attn_kernel<<<NWIN, 256, ATTN_SMEM>>>();

    // projection GEMM: [131072,384] @ [384,384] -> d_out
    gemm_tf32<<<dim3(3, MTOT / 128), 256, GEMM_SMEM>>>(attn, wt_proj, proj_b, (float*)d_out, CDIM);
}

// round 5
// speedup vs baseline: 7.5618x; 1.1036x over previous
#include <cuda_runtime.h>
#include <cstdint>
#include <math.h>

// Problem constants
#define NWIN 2048
#define NTOK 64
#define CDIM 384
#define NH   12
#define HD   32
#define MTOT (NWIN * NTOK)          // 131072 rows

// ---------------------------------------------------------------------------
// Device scratch
// ---------------------------------------------------------------------------
__device__ float g_x32[(size_t)MTOT * CDIM];           // x pre-rounded to tf32
__device__ float g_qkv[(size_t)MTOT * 3 * CDIM];       // [M,1152] tf32 bits
__device__ float g_attn[(size_t)MTOT * CDIM];          // [M,384]  tf32 bits
__device__ float g_bias[NH * NTOK * NTOK];             // fp32
__device__ float g_wt_qkv[(size_t)3 * CDIM * CDIM];    // [1152,384] K-major tf32
__device__ float g_wt_proj[(size_t)CDIM * CDIM];       // [384,384]  K-major tf32

__device__ __forceinline__ uint32_t f2tf32(float v) {
    uint32_t r;
    asm("cvt.rna.tf32.f32 %0, %1;" : "=r"(r) : "f"(v));
    return r;
}
__device__ __forceinline__ float f2tf32f(float v) { return __uint_as_float(f2tf32(v)); }

__device__ __forceinline__ void mma_tf32(float* d, const uint32_t* a, const uint32_t* b) {
    asm volatile(
        "mma.sync.aligned.m16n8k8.row.col.f32.tf32.tf32.f32 "
        "{%0,%1,%2,%3}, {%4,%5,%6,%7}, {%8,%9}, {%0,%1,%2,%3};"
        : "+f"(d[0]), "+f"(d[1]), "+f"(d[2]), "+f"(d[3])
        : "r"(a[0]), "r"(a[1]), "r"(a[2]), "r"(a[3]), "r"(b[0]), "r"(b[1]));
}
__device__ __forceinline__ uint32_t smem_u32(const void* p) {
    uint32_t a;
    asm("{ .reg .u64 t; cvta.to.shared.u64 t, %1; cvt.u32.u64 %0, t; }" : "=r"(a) : "l"(p));
    return a;
}
__device__ __forceinline__ void cp16(uint32_t dst, const void* src) {
    asm volatile("cp.async.cg.shared.global [%0], [%1], 16;" :: "r"(dst), "l"(src));
}
#define CP_COMMIT() asm volatile("cp.async.commit_group;" ::: "memory")
#define CP_WAIT(N)  asm volatile("cp.async.wait_group %0;" :: "n"(N) : "memory")

// ---------------------------------------------------------------------------
// x -> tf32 pre-round
// ---------------------------------------------------------------------------
__global__ void convert_x_kernel(const float* __restrict__ in) {
    size_t i = ((size_t)blockIdx.x * blockDim.x + threadIdx.x) * 4;
    if (i >= (size_t)MTOT * CDIM) return;
    float4 v = *(const float4*)(in + i);
    float4 o;
    o.x = f2tf32f(v.x); o.y = f2tf32f(v.y); o.z = f2tf32f(v.z); o.w = f2tf32f(v.w);
    *(float4*)(g_x32 + i) = o;
}

// ---------------------------------------------------------------------------
// weight transpose + tf32 round:  out[N,K] = tf32(in[K,N])
// ---------------------------------------------------------------------------
__global__ void transpose_kernel(const float* __restrict__ in, float* __restrict__ out,
                                 int K, int N) {
    __shared__ float tl[32][33];
    int n0 = blockIdx.x * 32, k0 = blockIdx.y * 32;
    int x = threadIdx.x, y = threadIdx.y;
#pragma unroll
    for (int j = y; j < 32; j += 8) tl[j][x] = in[(size_t)(k0 + j) * N + n0 + x];
    __syncthreads();
#pragma unroll
    for (int j = y; j < 32; j += 8) out[(size_t)(n0 + j) * K + k0 + x] = f2tf32f(tl[x][j]);
}

// ---------------------------------------------------------------------------
// relative position bias table (fp32)
// ---------------------------------------------------------------------------
__global__ void bias_kernel(const float* __restrict__ w1, const float* __restrict__ b1,
                            const float* __restrict__ w2, const float* __restrict__ b2) {
    int idx = blockIdx.x * blockDim.x + threadIdx.x;
    if (idx >= NTOK * NTOK) return;
    int n = idx / NTOK, m = idx % NTOK;
    float r0 = (float)((n >> 4) & 3) - (float)((m >> 4) & 3);
    float r1 = (float)((n >> 2) & 3) - (float)((m >> 2) & 3);
    float r2 = (float)(n & 3)        - (float)(m & 3);

    float outh[NH];
#pragma unroll
    for (int h = 0; h < NH; h++) outh[h] = b2[h];
    for (int j = 0; j < 64; j++) {
        float hj = fmaf(r0, w1[j], fmaf(r1, w1[64 + j], fmaf(r2, w1[128 + j], b1[j])));
        hj = fmaxf(hj, 0.0f);
#pragma unroll
        for (int h = 0; h < NH; h++) outh[h] = fmaf(hj, w2[j * NH + h], outh[h]);
    }
#pragma unroll
    for (int h = 0; h < NH; h++) g_bias[h * NTOK * NTOK + idx] = outh[h];
}

// ---------------------------------------------------------------------------
// tf32 mma.sync GEMM, 3-stage cp.async ring, zero CVT in mainloop.
// out[M, ldc] = A[M,384] @ Bt[N,384]^T + bias   (A, Bt hold tf32 bits)
// CTA tile 128x128, 8 warps (2Mx4N), warp tile 64x32, K-chunk 32.
// smem floats: A stages @ st*4096, B stages @ 12288 + st*4096 (3 stages, 96KB)
// ROUND_OUT: store outputs tf32-rounded (for operands of downstream mma).
// ---------------------------------------------------------------------------
#define KC 32
#define NCH (CDIM / KC)   // 12
#define GEMM_SMEM (24576 * 4)   // 96 KB

template <bool ROUND_OUT>
__global__ void __launch_bounds__(256, 2)
gemm_tf32(const float* __restrict__ A, const float* __restrict__ Bt,
          const float* __restrict__ bias, float* __restrict__ out, int ldc) {
    extern __shared__ float dsm[];

    const int t    = threadIdx.x;
    const int wid  = t >> 5, lane = t & 31;
    const int wm   = wid & 1;
    const int wn   = wid >> 1;
    const int n0   = blockIdx.x * 128;
    const int m0   = blockIdx.y * 128;
    const int lrow = lane >> 2;
    const int lcol = lane & 3;

    const uint32_t sbase = smem_u32(dsm);

    float acc[4][4][4];
#pragma unroll
    for (int i = 0; i < 4; i++)
#pragma unroll
        for (int j = 0; j < 4; j++)
#pragma unroll
            for (int r = 0; r < 4; r++) acc[i][j][r] = 0.0f;

    const int ldr = t >> 3;            // 0..31
    const int ldg = t & 7;             // 0..7 (16B group)

    // precomputed fragment row offsets (in floats)
    int rowa[4], rowb[4];
#pragma unroll
    for (int mt = 0; mt < 4; mt++) rowa[mt] = (wm * 64 + mt * 16 + lrow) * 32 + lcol;
#pragma unroll
    for (int nt = 0; nt < 4; nt++) rowb[nt] = (wn * 32 + nt * 8 + lrow) * 32 + lcol;

#define ISSUE(ch, st) do {                                                              \
        int _k0 = (ch) * KC;                                                            \
        _Pragma("unroll")                                                               \
        for (int _i = 0; _i < 4; _i++) {                                                \
            int _row = ldr + _i * 32;                                                   \
            int _sg  = ldg ^ (_row & 7);                                                \
            uint32_t _off = (uint32_t)((st) * 16384 + (_row * 32 + _sg * 4) * 4);       \
            cp16(sbase + _off,         A  + (size_t)(m0 + _row) * CDIM + _k0 + ldg * 4); \
            cp16(sbase + 49152 + _off, Bt + (size_t)(n0 + _row) * CDIM + _k0 + ldg * 4); \
        }                                                                               \
        CP_COMMIT();                                                                    \
    } while (0)

#define COMPUTE(st) do {                                                                \
        const float* As_ = dsm + (st) * 4096;                                           \
        const float* Bs_ = dsm + 12288 + (st) * 4096;                                   \
        _Pragma("unroll")                                                               \
        for (int ks = 0; ks < 4; ks++) {                                                \
            const int go0 = ((2 * ks) ^ lrow) * 4;                                      \
            const int go1 = ((2 * ks + 1) ^ lrow) * 4;                                  \
            uint32_t afr[4][4], bfr[4][2];                                              \
            _Pragma("unroll")                                                           \
            for (int mt = 0; mt < 4; mt++) {                                            \
                afr[mt][0] = __float_as_uint(As_[rowa[mt] + go0]);                      \
                afr[mt][1] = __float_as_uint(As_[rowa[mt] + 256 + go0]);                \
                afr[mt][2] = __float_as_uint(As_[rowa[mt] + go1]);                      \
                afr[mt][3] = __float_as_uint(As_[rowa[mt] + 256 + go1]);                \
            }                                                                           \
            _Pragma("unroll")                                                           \
            for (int nt = 0; nt < 4; nt++) {                                            \
                bfr[nt][0] = __float_as_uint(Bs_[rowb[nt] + go0]);                      \
                bfr[nt][1] = __float_as_uint(Bs_[rowb[nt] + go1]);                      \
            }                                                                           \
            _Pragma("unroll")                                                           \
            for (int mt = 0; mt < 4; mt++)                                              \
                _Pragma("unroll")                                                       \
                for (int nt = 0; nt < 4; nt++)                                          \
                    mma_tf32(acc[mt][nt], afr[mt], bfr[nt]);                            \
        }                                                                               \
    } while (0)

#define STEP(c, st, stnext) do {                                                        \
        if ((c) == NCH - 1) { CP_WAIT(0); } else { CP_WAIT(1); }                        \
        __syncthreads();                                                                \
        if ((c) + 2 < NCH) ISSUE((c) + 2, stnext);                                      \
        COMPUTE(st);                                                                    \
    } while (0)

    ISSUE(0, 0);
    ISSUE(1, 1);
#pragma unroll
    for (int c3 = 0; c3 < NCH; c3 += 3) {
        STEP(c3 + 0, 0, 2);
        STEP(c3 + 1, 1, 0);
        STEP(c3 + 2, 2, 1);
    }

#pragma unroll
    for (int mt = 0; mt < 4; mt++) {
#pragma unroll
        for (int nt = 0; nt < 4; nt++) {
            int row = m0 + wm * 64 + mt * 16 + lrow;
            int col = n0 + wn * 32 + nt * 8 + lcol * 2;
            float2 bv = *(const float2*)(bias + col);
            float2 o0, o1;
            if (ROUND_OUT) {
                o0.x = f2tf32f(acc[mt][nt][0] + bv.x); o0.y = f2tf32f(acc[mt][nt][1] + bv.y);
                o1.x = f2tf32f(acc[mt][nt][2] + bv.x); o1.y = f2tf32f(acc[mt][nt][3] + bv.y);
            } else {
                o0.x = acc[mt][nt][0] + bv.x; o0.y = acc[mt][nt][1] + bv.y;
                o1.x = acc[mt][nt][2] + bv.x; o1.y = acc[mt][nt][3] + bv.y;
            }
            *(float2*)(out + (size_t)row * ldc + col)       = o0;
            *(float2*)(out + (size_t)(row + 8) * ldc + col) = o1;
        }
    }
#undef STEP
#undef COMPUTE
#undef ISSUE
}

// ---------------------------------------------------------------------------
// Tensor-core attention per window. Block = 1 window, 256 thr = 2 teams x 4 warps.
// q/k/v arrive tf32-pre-rounded; only P needs CVT.
// Team smem (floats): qs[64][36], ks[64][36], vt[32][68], Ss[64][68] = 11136
// ---------------------------------------------------------------------------
#define TEAM_F 11136
#define ATTN_SMEM (2 * TEAM_F * 4)

__global__ void __launch_bounds__(256, 2)
attn_kernel() {
    extern __shared__ float dsm[];
    const int b    = blockIdx.x;
    const int t    = threadIdx.x;
    const int team = t >> 7;
    const int lt   = t & 127;
    const int w    = lt >> 5;
    const int lane = t & 31;
    const int lrow = lane >> 2;
    const int lcol = lane & 3;

    float* qs = dsm + team * TEAM_F;   // [64][36]
    float* ks = qs + 64 * 36;          // [64][36]
    float* vt = ks + 64 * 36;          // [32][68]  (d, m)
    float* Ss = vt + 32 * 68;          // [64][68]

    const float scale = 0.17677669529663687f;  // 1/sqrt(32)
    const float* qkvb = g_qkv + (size_t)b * NTOK * (3 * CDIM);

    for (int hi = 0; hi < 6; hi++) {
        const int h = hi * 2 + team;
        const int qoff = h * HD, koff = CDIM + h * HD, voff = 2 * CDIM + h * HD;

        for (int i = lt; i < 512; i += 128) {
            int n = i >> 3, c4 = i & 7;
            const float* rowp = qkvb + (size_t)n * (3 * CDIM);
            float4 qv = *(const float4*)(rowp + qoff + c4 * 4);
            float4 kv = *(const float4*)(rowp + koff + c4 * 4);
            float4 vv = *(const float4*)(rowp + voff + c4 * 4);
            float* qd = qs + n * 36 + c4 * 4;
            float* kd = ks + n * 36 + c4 * 4;
            qd[0] = qv.x; qd[1] = qv.y; qd[2] = qv.z; qd[3] = qv.w;
            kd[0] = kv.x; kd[1] = kv.y; kd[2] = kv.z; kd[3] = kv.w;
            int d0 = c4 * 4;
            vt[(d0 + 0) * 68 + n] = vv.x;
            vt[(d0 + 1) * 68 + n] = vv.y;
            vt[(d0 + 2) * 68 + n] = vv.z;
            vt[(d0 + 3) * 68 + n] = vv.w;
        }
        __syncthreads();

        // ---- S = Q K^T
        float sacc[8][4];
#pragma unroll
        for (int nt = 0; nt < 8; nt++)
#pragma unroll
            for (int r = 0; r < 4; r++) sacc[nt][r] = 0.0f;

#pragma unroll
        for (int kc = 0; kc < 4; kc++) {
            const int kk = kc * 8;
            int row0 = w * 16 + lrow;
            uint32_t af[4];
            af[0] = __float_as_uint(qs[row0 * 36 + kk + lcol]);
            af[1] = __float_as_uint(qs[(row0 + 8) * 36 + kk + lcol]);
            af[2] = __float_as_uint(qs[row0 * 36 + kk + 4 + lcol]);
            af[3] = __float_as_uint(qs[(row0 + 8) * 36 + kk + 4 + lcol]);
#pragma unroll
            for (int nt = 0; nt < 8; nt++) {
                int krow = nt * 8 + lrow;
                uint32_t bf[2];
                bf[0] = __float_as_uint(ks[krow * 36 + kk + lcol]);
                bf[1] = __float_as_uint(ks[krow * 36 + kk + 4 + lcol]);
                mma_tf32(sacc[nt], af, bf);
            }
        }
        const float* bh = g_bias + h * NTOK * NTOK;
        {
            int row = w * 16 + lrow;
#pragma unroll
            for (int nt = 0; nt < 8; nt++) {
                int col = nt * 8 + lcol * 2;
                float2 b0 = *(const float2*)(bh + row * 64 + col);
                float2 b1 = *(const float2*)(bh + (row + 8) * 64 + col);
                Ss[row * 68 + col]           = fmaf(sacc[nt][0], scale, b0.x);
                Ss[row * 68 + col + 1]       = fmaf(sacc[nt][1], scale, b0.y);
                Ss[(row + 8) * 68 + col]     = fmaf(sacc[nt][2], scale, b1.x);
                Ss[(row + 8) * 68 + col + 1] = fmaf(sacc[nt][3], scale, b1.y);
            }
        }
        __syncthreads();

        // ---- softmax: 2 threads per row
        {
            int r = lt >> 1;
            float* Sr = Ss + r * 68 + (lt & 1) * 32;
            float mx = -1e30f;
#pragma unroll 8
            for (int m = 0; m < 32; m++) mx = fmaxf(mx, Sr[m]);
            mx = fmaxf(mx, __shfl_xor_sync(0xFFFFFFFFu, mx, 1));
            float sum = 0.0f;
#pragma unroll 8
            for (int m = 0; m < 32; m++) { float e = __expf(Sr[m] - mx); Sr[m] = e; sum += e; }
            sum += __shfl_xor_sync(0xFFFFFFFFu, sum, 1);
            float inv = 1.0f / sum;
#pragma unroll 8
            for (int m = 0; m < 32; m++) Sr[m] *= inv;
        }
        __syncthreads();

        // ---- O = P V
        float oacc[4][4];
#pragma unroll
        for (int nt = 0; nt < 4; nt++)
#pragma unroll
            for (int r = 0; r < 4; r++) oacc[nt][r] = 0.0f;

#pragma unroll
        for (int kc = 0; kc < 8; kc++) {
            const int kk = kc * 8;
            int row0 = w * 16 + lrow;
            uint32_t pf[4];
            pf[0] = f2tf32(Ss[row0 * 68 + kk + lcol]);
            pf[1] = f2tf32(Ss[(row0 + 8) * 68 + kk + lcol]);
            pf[2] = f2tf32(Ss[row0 * 68 + kk + 4 + lcol]);
            pf[3] = f2tf32(Ss[(row0 + 8) * 68 + kk + 4 + lcol]);
#pragma unroll
            for (int nt = 0; nt < 4; nt++) {
                int dd = nt * 8 + lrow;
                uint32_t vf[2];
                vf[0] = __float_as_uint(vt[dd * 68 + kk + lcol]);
                vf[1] = __float_as_uint(vt[dd * 68 + kk + 4 + lcol]);
                mma_tf32(oacc[nt], pf, vf);
            }
        }
        {
            float* og = g_attn + (size_t)b * NTOK * CDIM + h * HD;
            int row = w * 16 + lrow;
#pragma unroll
            for (int nt = 0; nt < 4; nt++) {
                int col = nt * 8 + lcol * 2;
                float2 o0 = make_float2(f2tf32f(oacc[nt][0]), f2tf32f(oacc[nt][1]));
                float2 o1 = make_float2(f2tf32f(oacc[nt][2]), f2tf32f(oacc[nt][3]));
                *(float2*)(og + (size_t)row * CDIM + col)       = o0;
                *(float2*)(og + (size_t)(row + 8) * CDIM + col) = o1;
            }
        }
        __syncthreads();
    }
}

// ---------------------------------------------------------------------------
extern "C" void kernel_launch(void* const* d_in, const int* in_sizes, int n_in,
                              void* d_out, int out_size) {
    const float* x      = (const float*)d_in[0];
    const float* qkv_w  = (const float*)d_in[1];
    const float* qkv_b  = (const float*)d_in[2];
    const float* proj_w = (const float*)d_in[3];
    const float* proj_b = (const float*)d_in[4];
    const float* mlp_w1 = (const float*)d_in[5];
    const float* mlp_b1 = (const float*)d_in[6];
    const float* mlp_w2 = (const float*)d_in[7];
    const float* mlp_b2 = (const float*)d_in[8];

    float* wt_qkv;  cudaGetSymbolAddress((void**)&wt_qkv,  g_wt_qkv);
    float* wt_proj; cudaGetSymbolAddress((void**)&wt_proj, g_wt_proj);
    float* qkv;     cudaGetSymbolAddress((void**)&qkv,     g_qkv);
    float* attn;    cudaGetSymbolAddress((void**)&attn,    g_attn);
    float* x32;     cudaGetSymbolAddress((void**)&x32,     g_x32);

    convert_x_kernel<<<(MTOT * CDIM / 4 + 255) / 256, 256>>>(x);
    transpose_kernel<<<dim3(3 * CDIM / 32, CDIM / 32), dim3(32, 8)>>>(qkv_w, wt_qkv, CDIM, 3 * CDIM);
    transpose_kernel<<<dim3(CDIM / 32, CDIM / 32), dim3(32, 8)>>>(proj_w, wt_proj, CDIM, CDIM);
    bias_kernel<<<16, 256>>>(mlp_w1, mlp_b1, mlp_w2, mlp_b2);

    cudaFuncSetAttribute(gemm_tf32<true>,  cudaFuncAttributeMaxDynamicSharedMemorySize, GEMM_SMEM);
    cudaFuncSetAttribute(gemm_tf32<false>, cudaFuncAttributeMaxDynamicSharedMemorySize, GEMM_SMEM);
    cudaFuncSetAttribute(attn_kernel, cudaFuncAttributeMaxDynamicSharedMemorySize, ATTN_SMEM);

    // QKV GEMM: [131072,384] @ [384,1152] -> tf32-rounded qkv
    gemm_tf32<true><<<dim3(9, MTOT / 128), 256, GEMM_SMEM>>>(x32, wt_qkv, qkv_b, qkv, 3 * CDIM);

    // attention (tensor cores) -> tf32-rounded attn
    attn_kernel<<<NWIN, 256, ATTN_SMEM>>>();

    // projection GEMM: [131072,384] @ [384,384] -> d_out (fp32)
    gemm_tf32<false><<<dim3(3, MTOT / 128), 256, GEMM_SMEM>>>(attn, wt_proj, proj_b, (float*)d_out, CDIM);
}